// round 15
// baseline (speedup 1.0000x reference)
#include <cuda_runtime.h>
#include <cstdint>

// Problem constants
#define B    32
#define NCHUNK_B 4                 // batch pipeline chunks
#define CB   (B / NCHUNK_B)        // 8 images per chunk
#define H    768
#define W    768
#define IMG  (H * W)               // 589824
#define NPIX (B * IMG)             // 18874368
#define RSM_K 35

// Pass-1 row chunking: 8 chunks of 96 rows (+17/+16 halo, amp 1.35)
#define CHUNKS 8
#define CHUNK_ROWS (H / CHUNKS)    // 96

// Intermediate: one byte per pixel.
//   bits 0-5 : vertical 35-window popcount (0..35)
//   bit  6   : center mask bit
//   bit  7   : vertical 31-window "any" flag
__device__ uint8_t g_packed[NPIX];

// ---------------------------------------------------------------------------
// Pass 1: vertical sliding bit-window per column, explicit load batching for
// MLP. grid: CB * 3 * CHUNKS = 192 blocks of 256 threads per batch chunk.
// ---------------------------------------------------------------------------
__global__ __launch_bounds__(256) void pass1_vertical(const float* __restrict__ masks,
                                                      int b_base) {
    const int tid   = threadIdx.x;
    const int chunk = blockIdx.x & (CHUNKS - 1);
    int tmp         = blockIdx.x >> 3;          // log2(CHUNKS)=3
    const int xb    = tmp % 3;
    const int b     = b_base + tmp / 3;
    const int x     = xb * 256 + tid;

    const int r0 = chunk * CHUNK_ROWS;

    const float*  ibase = masks    + (size_t)b * IMG + x;
    uint8_t*      obase = g_packed + (size_t)b * IMG + x;

    const uint64_t M35 = (1ULL << 35) - 1;
    const uint64_t M31 = (1ULL << 31) - 1;

    uint64_t bits = 0;

    // Prologue: rows r0-17 .. r0+16 (34 rows), two batches of 17 loads
    #pragma unroll 1
    for (int pb = 0; pb < 34; pb += 17) {
        float fv[17];
        #pragma unroll
        for (int i = 0; i < 17; ++i) {
            const int t = r0 - 17 + pb + i;     // t <= r0+16 <= 688 < H
            fv[i] = 0.0f;
            if (t >= 0) fv[i] = ibase[(size_t)t * W];
        }
        #pragma unroll
        for (int i = 0; i < 17; ++i)
            bits = (bits << 1) | (uint64_t)(fv[i] > 0.5f);
    }

    // Emit loop: batches of 8 rows; 8 outstanding LDGs per warp per batch.
    #pragma unroll 1
    for (int yb = 0; yb < CHUNK_ROWS; yb += 8) {
        float fv[8];
        #pragma unroll
        for (int i = 0; i < 8; ++i) {
            const int t = r0 + yb + i + 17;
            fv[i] = 0.0f;
            if (t < H) fv[i] = ibase[(size_t)t * W];
        }
        #pragma unroll
        for (int i = 0; i < 8; ++i) {
            bits = (bits << 1) | (uint64_t)(fv[i] > 0.5f);
            const int y = r0 + yb + i;
            uint32_t cnt    = (uint32_t)__popcll(bits & M35);          // rows y-17..y+17
            uint32_t center = (uint32_t)((bits >> 17) & 1ULL);         // row y
            uint32_t flag   = (((bits >> 2) & M31) != 0ULL) ? 1u : 0u; // rows y-15..y+15
            obase[(size_t)y * W] = (uint8_t)(cnt | (center << 6) | (flag << 7));
        }
    }
}

// ---------------------------------------------------------------------------
// Pass 2: per-row horizontal windows via one fused prefix sum.
// 192 threads per block, one row per block, 4 outputs per thread.
// Two __syncthreads; cross-warp offsets derived per-thread from broadcast LDS.
// grid: CB * H = 6144 blocks per batch chunk.
// ---------------------------------------------------------------------------
#define PAD 20

__global__ __launch_bounds__(192) void pass2_horizontal(float* __restrict__ out_rsm,
                                                        float* __restrict__ out_pfm,
                                                        int b_base) {
    __shared__ __align__(16) uint32_t sPp[PAD + W + 17];  // padded fused prefix
    __shared__ uint32_t sWarp[6];

    const int tid  = threadIdx.x;
    const int lane = tid & 31;
    const int wid  = tid >> 5;
    const int row  = b_base * H + blockIdx.x;   // global row = b*H + y
    const int x0   = tid * 4;

    // One u32 = this thread's 4 packed bytes (byte j -> x = x0 + j)
    const uint32_t w = ((const uint32_t*)(g_packed + (size_t)row * W))[tid];

    if (tid < PAD) sPp[tid] = 0;

    // Unpack: v = (cnt << 16) | flag
    uint32_t v0, v1, v2, v3;
    {
        uint32_t c0 = (w      ) & 63u, f0 = (w >> 7 ) & 1u;
        uint32_t c1 = (w >> 8 ) & 63u, f1 = (w >> 15) & 1u;
        uint32_t c2 = (w >> 16) & 63u, f2 = (w >> 23) & 1u;
        uint32_t c3 = (w >> 24) & 63u, f3 = (w >> 31);
        v0 = c0 * 65536u + f0;
        v1 = c1 * 65536u + f1;
        v2 = c2 * 65536u + f2;
        v3 = c3 * 65536u + f3;
    }
    const uint32_t s0 = v0;
    const uint32_t s1 = s0 + v1;
    const uint32_t s2 = s1 + v2;
    const uint32_t s3 = s2 + v3;

    // Warp inclusive scan of per-thread totals
    uint32_t sc = s3;
    #pragma unroll
    for (int d = 1; d < 32; d <<= 1) {
        uint32_t y = __shfl_up_sync(0xFFFFFFFFu, sc, d);
        if (lane >= d) sc += y;
    }
    if (lane == 31) sWarp[wid] = sc;
    __syncthreads();

    // Every thread derives its cross-warp exclusive offset and the row total
    // from the 6 per-warp totals (broadcast LDS, no serial thread, no barrier).
    uint32_t wt0 = sWarp[0], wt1 = sWarp[1], wt2 = sWarp[2];
    uint32_t wt3 = sWarp[3], wt4 = sWarp[4], wt5 = sWarp[5];
    uint32_t pre[6];
    pre[0] = 0;
    pre[1] = wt0;
    pre[2] = pre[1] + wt1;
    pre[3] = pre[2] + wt2;
    pre[4] = pre[3] + wt3;
    pre[5] = pre[4] + wt4;
    const uint32_t tot  = pre[5] + wt5;
    const uint32_t excl = (sc - s3) + pre[wid];

    // Inclusive prefix at x0..x0+3 (vector STS)
    {
        uint4 p;
        p.x = excl + s0;
        p.y = excl + s1;
        p.z = excl + s2;
        p.w = excl + s3;
        *(uint4*)&sPp[PAD + x0] = p;
    }
    // Right pad: replicate row total P[W-1]
    if (tid < 17) sPp[PAD + W + tid] = tot;
    __syncthreads();

    // Window reads (indices pre-shifted by PAD=20):
    //   lo35_j = sPp[x0+j+2], lo31_j = sPp[x0+j+4]
    //   hi31_j = sPp[x0+j+35], hi35_j = sPp[x0+j+37]
    const uint2 A01 = *(const uint2*)&sPp[x0 + 2];
    const uint4 A25 = *(const uint4*)&sPp[x0 + 4];
    const uint32_t b35 = sPp[x0 + 35];
    const uint4 B69 = *(const uint4*)&sPp[x0 + 36];
    const uint32_t b40 = sPp[x0 + 40];

    const float inv = 1.0f / (float)(RSM_K * RSM_K);

    // hi - lo has no cross-field borrow (both fields monotone)
    uint32_t d35_0 = B69.y - A01.x;
    uint32_t d35_1 = B69.z - A01.y;
    uint32_t d35_2 = B69.w - A25.x;
    uint32_t d35_3 = b40   - A25.y;

    uint32_t f31_0 = (b35   - A25.x) & 0xFFFFu;
    uint32_t f31_1 = (B69.x - A25.y) & 0xFFFFu;
    uint32_t f31_2 = (B69.y - A25.z) & 0xFFFFu;
    uint32_t f31_3 = (B69.z - A25.w) & 0xFFFFu;

    float4 rsm4;
    rsm4.x = (float)(d35_0 >> 16) * inv;
    rsm4.y = (float)(d35_1 >> 16) * inv;
    rsm4.z = (float)(d35_2 >> 16) * inv;
    rsm4.w = (float)(d35_3 >> 16) * inv;

    // pfm = center ? 1 : (f31 ? 0 : 2) == center + 2*(f31==0)
    float4 pfm4;
    pfm4.x = (float)(((w >> 6)  & 1u) + ((f31_0 == 0u) ? 2u : 0u));
    pfm4.y = (float)(((w >> 14) & 1u) + ((f31_1 == 0u) ? 2u : 0u));
    pfm4.z = (float)(((w >> 22) & 1u) + ((f31_2 == 0u) ? 2u : 0u));
    pfm4.w = (float)(((w >> 30) & 1u) + ((f31_3 == 0u) ? 2u : 0u));

    // Streaming stores: outputs are never re-read; keep L2 for g_packed.
    __stcs((float4*)(out_rsm + (size_t)row * W + x0), rsm4);
    __stcs((float4*)(out_pfm + (size_t)row * W + x0), pfm4);
}

// ---------------------------------------------------------------------------
// Static stream/event setup: created once at module load, before the harness's
// first memory checkpoint. No per-call state; identical DAG every call.
// ---------------------------------------------------------------------------
namespace {
struct StreamSetup {
    cudaStream_t s1 = nullptr;
    cudaEvent_t  ev[NCHUNK_B] = {};
    cudaEvent_t  evJoin = nullptr;
    StreamSetup() {
        cudaStreamCreateWithFlags(&s1, cudaStreamNonBlocking);
        for (int i = 0; i < NCHUNK_B; ++i)
            cudaEventCreateWithFlags(&ev[i], cudaEventDisableTiming);
        cudaEventCreateWithFlags(&evJoin, cudaEventDisableTiming);
    }
};
StreamSetup g_ss;
}

extern "C" void kernel_launch(void* const* d_in, const int* in_sizes, int n_in,
                              void* d_out, int out_size) {
    const float* masks = (const float*)d_in[0];
    float* out = (float*)d_out;
    float* out_rsm = out;
    float* out_pfm = out + NPIX;

    // Producer-consumer pipeline:
    //   stream 0: pass1(chunk 0..3), event after each
    //   stream 1: pass2(chunk i) gated on event i
    // Steady state overlaps read-heavy pass1(i+1) with write-heavy pass2(i).
    for (int i = 0; i < NCHUNK_B; ++i) {
        pass1_vertical<<<CB * 3 * CHUNKS, 256>>>(masks, i * CB);
        cudaEventRecord(g_ss.ev[i], 0);
    }
    for (int i = 0; i < NCHUNK_B; ++i) {
        cudaStreamWaitEvent(g_ss.s1, g_ss.ev[i], 0);
        pass2_horizontal<<<CB * H, 192, 0, g_ss.s1>>>(out_rsm, out_pfm, i * CB);
    }

    // Join: stream 0 waits for the consumer chain to finish.
    cudaEventRecord(g_ss.evJoin, g_ss.s1);
    cudaStreamWaitEvent(0, g_ss.evJoin, 0);
}

// round 16
// speedup vs baseline: 1.3617x; 1.3617x over previous
#include <cuda_runtime.h>
#include <cstdint>

// Problem constants
#define B    32
#define HB   16                    // half batch
#define H    768
#define W    768
#define IMG  (H * W)               // 589824
#define NPIX (B * IMG)             // 18874368
#define RSM_K 35

// Pass-1 row chunking: 8 chunks of 96 rows (+17/+16 halo, amp 1.35)
#define CHUNKS 8
#define CHUNK_ROWS (H / CHUNKS)    // 96

// Intermediate: one byte per pixel.
//   bits 0-5 : vertical 35-window popcount (0..35)
//   bit  6   : center mask bit
//   bit  7   : vertical 31-window "any" flag
__device__ uint8_t g_packed[NPIX];

// ---------------------------------------------------------------------------
// Pass 1: vertical sliding bit-window per column, explicit load batching for
// MLP. grid: HB * 3 * CHUNKS = 384 blocks of 256 threads per half batch.
// ---------------------------------------------------------------------------
__global__ __launch_bounds__(256) void pass1_vertical(const float* __restrict__ masks,
                                                      int b_base) {
    const int tid   = threadIdx.x;
    const int chunk = blockIdx.x & (CHUNKS - 1);
    int tmp         = blockIdx.x >> 3;          // log2(CHUNKS)=3
    const int xb    = tmp % 3;
    const int b     = b_base + tmp / 3;
    const int x     = xb * 256 + tid;

    const int r0 = chunk * CHUNK_ROWS;

    const float*  ibase = masks    + (size_t)b * IMG + x;
    uint8_t*      obase = g_packed + (size_t)b * IMG + x;

    const uint64_t M35 = (1ULL << 35) - 1;
    const uint64_t M31 = (1ULL << 31) - 1;

    uint64_t bits = 0;

    // Prologue: rows r0-17 .. r0+16 (34 rows), two batches of 17 loads
    #pragma unroll 1
    for (int pb = 0; pb < 34; pb += 17) {
        float fv[17];
        #pragma unroll
        for (int i = 0; i < 17; ++i) {
            const int t = r0 - 17 + pb + i;     // t <= r0+16 <= 688 < H
            fv[i] = 0.0f;
            if (t >= 0) fv[i] = ibase[(size_t)t * W];
        }
        #pragma unroll
        for (int i = 0; i < 17; ++i)
            bits = (bits << 1) | (uint64_t)(fv[i] > 0.5f);
    }

    // Emit loop: batches of 8 rows; 8 outstanding LDGs per warp per batch.
    #pragma unroll 1
    for (int yb = 0; yb < CHUNK_ROWS; yb += 8) {
        float fv[8];
        #pragma unroll
        for (int i = 0; i < 8; ++i) {
            const int t = r0 + yb + i + 17;
            fv[i] = 0.0f;
            if (t < H) fv[i] = ibase[(size_t)t * W];
        }
        #pragma unroll
        for (int i = 0; i < 8; ++i) {
            bits = (bits << 1) | (uint64_t)(fv[i] > 0.5f);
            const int y = r0 + yb + i;
            uint32_t cnt    = (uint32_t)__popcll(bits & M35);          // rows y-17..y+17
            uint32_t center = (uint32_t)((bits >> 17) & 1ULL);         // row y
            uint32_t flag   = (((bits >> 2) & M31) != 0ULL) ? 1u : 0u; // rows y-15..y+15
            obase[(size_t)y * W] = (uint8_t)(cnt | (center << 6) | (flag << 7));
        }
    }
}

// ---------------------------------------------------------------------------
// Pass 2: per-row horizontal windows via one fused prefix sum.
// 192 threads per block, one row per block, 4 outputs per thread.
// Two __syncthreads; cross-warp offsets derived per-thread from broadcast LDS.
// grid: HB * H = 12288 blocks per half batch.
// ---------------------------------------------------------------------------
#define PAD 20

__global__ __launch_bounds__(192) void pass2_horizontal(float* __restrict__ out_rsm,
                                                        float* __restrict__ out_pfm,
                                                        int b_base) {
    __shared__ __align__(16) uint32_t sPp[PAD + W + 17];  // padded fused prefix
    __shared__ uint32_t sWarp[6];

    const int tid  = threadIdx.x;
    const int lane = tid & 31;
    const int wid  = tid >> 5;
    const int row  = b_base * H + blockIdx.x;   // global row = b*H + y
    const int x0   = tid * 4;

    // One u32 = this thread's 4 packed bytes (byte j -> x = x0 + j)
    const uint32_t w = ((const uint32_t*)(g_packed + (size_t)row * W))[tid];

    if (tid < PAD) sPp[tid] = 0;

    // Unpack: v = (cnt << 16) | flag
    uint32_t v0, v1, v2, v3;
    {
        uint32_t c0 = (w      ) & 63u, f0 = (w >> 7 ) & 1u;
        uint32_t c1 = (w >> 8 ) & 63u, f1 = (w >> 15) & 1u;
        uint32_t c2 = (w >> 16) & 63u, f2 = (w >> 23) & 1u;
        uint32_t c3 = (w >> 24) & 63u, f3 = (w >> 31);
        v0 = c0 * 65536u + f0;
        v1 = c1 * 65536u + f1;
        v2 = c2 * 65536u + f2;
        v3 = c3 * 65536u + f3;
    }
    const uint32_t s0 = v0;
    const uint32_t s1 = s0 + v1;
    const uint32_t s2 = s1 + v2;
    const uint32_t s3 = s2 + v3;

    // Warp inclusive scan of per-thread totals
    uint32_t sc = s3;
    #pragma unroll
    for (int d = 1; d < 32; d <<= 1) {
        uint32_t y = __shfl_up_sync(0xFFFFFFFFu, sc, d);
        if (lane >= d) sc += y;
    }
    if (lane == 31) sWarp[wid] = sc;
    __syncthreads();

    // Every thread derives its cross-warp exclusive offset and the row total
    // from the 6 per-warp totals (broadcast LDS, no serial thread, no barrier).
    uint32_t wt0 = sWarp[0], wt1 = sWarp[1], wt2 = sWarp[2];
    uint32_t wt3 = sWarp[3], wt4 = sWarp[4], wt5 = sWarp[5];
    uint32_t pre[6];
    pre[0] = 0;
    pre[1] = wt0;
    pre[2] = pre[1] + wt1;
    pre[3] = pre[2] + wt2;
    pre[4] = pre[3] + wt3;
    pre[5] = pre[4] + wt4;
    const uint32_t tot  = pre[5] + wt5;
    const uint32_t excl = (sc - s3) + pre[wid];

    // Inclusive prefix at x0..x0+3 (vector STS)
    {
        uint4 p;
        p.x = excl + s0;
        p.y = excl + s1;
        p.z = excl + s2;
        p.w = excl + s3;
        *(uint4*)&sPp[PAD + x0] = p;
    }
    // Right pad: replicate row total P[W-1]
    if (tid < 17) sPp[PAD + W + tid] = tot;
    __syncthreads();

    // Window reads (indices pre-shifted by PAD=20):
    //   lo35_j = sPp[x0+j+2], lo31_j = sPp[x0+j+4]
    //   hi31_j = sPp[x0+j+35], hi35_j = sPp[x0+j+37]
    const uint2 A01 = *(const uint2*)&sPp[x0 + 2];
    const uint4 A25 = *(const uint4*)&sPp[x0 + 4];
    const uint32_t b35 = sPp[x0 + 35];
    const uint4 B69 = *(const uint4*)&sPp[x0 + 36];
    const uint32_t b40 = sPp[x0 + 40];

    const float inv = 1.0f / (float)(RSM_K * RSM_K);

    // hi - lo has no cross-field borrow (both fields monotone)
    uint32_t d35_0 = B69.y - A01.x;
    uint32_t d35_1 = B69.z - A01.y;
    uint32_t d35_2 = B69.w - A25.x;
    uint32_t d35_3 = b40   - A25.y;

    uint32_t f31_0 = (b35   - A25.x) & 0xFFFFu;
    uint32_t f31_1 = (B69.x - A25.y) & 0xFFFFu;
    uint32_t f31_2 = (B69.y - A25.z) & 0xFFFFu;
    uint32_t f31_3 = (B69.z - A25.w) & 0xFFFFu;

    float4 rsm4;
    rsm4.x = (float)(d35_0 >> 16) * inv;
    rsm4.y = (float)(d35_1 >> 16) * inv;
    rsm4.z = (float)(d35_2 >> 16) * inv;
    rsm4.w = (float)(d35_3 >> 16) * inv;

    // pfm = center ? 1 : (f31 ? 0 : 2) == center + 2*(f31==0)
    float4 pfm4;
    pfm4.x = (float)(((w >> 6)  & 1u) + ((f31_0 == 0u) ? 2u : 0u));
    pfm4.y = (float)(((w >> 14) & 1u) + ((f31_1 == 0u) ? 2u : 0u));
    pfm4.z = (float)(((w >> 22) & 1u) + ((f31_2 == 0u) ? 2u : 0u));
    pfm4.w = (float)(((w >> 30) & 1u) + ((f31_3 == 0u) ? 2u : 0u));

    // Streaming stores: outputs are never re-read; keep L2 for g_packed.
    __stcs((float4*)(out_rsm + (size_t)row * W + x0), rsm4);
    __stcs((float4*)(out_pfm + (size_t)row * W + x0), pfm4);
}

// ---------------------------------------------------------------------------
// Static stream/event setup: created once at module load, before the harness's
// first memory checkpoint. No per-call state; identical DAG every call.
// ---------------------------------------------------------------------------
namespace {
struct StreamSetup {
    cudaStream_t s1 = nullptr;
    cudaEvent_t  ev0 = nullptr, evJoin = nullptr;
    StreamSetup() {
        cudaStreamCreateWithFlags(&s1, cudaStreamNonBlocking);
        cudaEventCreateWithFlags(&ev0, cudaEventDisableTiming);
        cudaEventCreateWithFlags(&evJoin, cudaEventDisableTiming);
    }
};
StreamSetup g_ss;
}

extern "C" void kernel_launch(void* const* d_in, const int* in_sizes, int n_in,
                              void* d_out, int out_size) {
    const float* masks = (const float*)d_in[0];
    float* out = (float*)d_out;
    float* out_rsm = out;
    float* out_pfm = out + NPIX;

    // Staggered half-batch pipeline:
    //   s0: pass1(h0) --ev0--> pass2(h0)
    //   s1:     (wait ev0) pass1(h1) --> pass2(h1)
    // Middle window overlaps write-heavy pass2(h0) with read-heavy pass1(h1).
    pass1_vertical<<<HB * 3 * CHUNKS, 256>>>(masks, 0);
    cudaEventRecord(g_ss.ev0, 0);

    cudaStreamWaitEvent(g_ss.s1, g_ss.ev0, 0);
    pass1_vertical<<<HB * 3 * CHUNKS, 256, 0, g_ss.s1>>>(masks, HB);
    pass2_horizontal<<<HB * H, 192, 0, g_ss.s1>>>(out_rsm, out_pfm, HB);

    pass2_horizontal<<<HB * H, 192>>>(out_rsm, out_pfm, 0);

    // Join: default stream waits for s1's chain.
    cudaEventRecord(g_ss.evJoin, g_ss.s1);
    cudaStreamWaitEvent(0, g_ss.evJoin, 0);
}

// round 17
// speedup vs baseline: 1.6597x; 1.2188x over previous
#include <cuda_runtime.h>
#include <cstdint>

// Problem constants
#define B    32
#define HB   16                    // half batch
#define H    768
#define W    768
#define IMG  (H * W)               // 589824
#define NPIX (B * IMG)             // 18874368
#define RSM_K 35

// Pass-1 row chunking: 8 chunks of 96 rows (+17/+16 halo, amp 1.35)
#define CHUNKS 8
#define CHUNK_ROWS (H / CHUNKS)    // 96

// Intermediate: one byte per pixel.
//   bits 0-5 : vertical 35-window popcount (0..35)
//   bit  6   : center mask bit
//   bit  7   : vertical 31-window "any" flag
__device__ uint8_t g_packed[NPIX];

// ---------------------------------------------------------------------------
// Pass 1: vertical sliding bit-window per column, explicit load batching for
// MLP (16-deep). grid: HB * 3 * CHUNKS = 384 blocks of 256 threads per half.
// ---------------------------------------------------------------------------
__global__ __launch_bounds__(256) void pass1_vertical(const float* __restrict__ masks,
                                                      int b_base) {
    const int tid   = threadIdx.x;
    const int chunk = blockIdx.x & (CHUNKS - 1);
    int tmp         = blockIdx.x >> 3;          // log2(CHUNKS)=3
    const int xb    = tmp % 3;
    const int b     = b_base + tmp / 3;
    const int x     = xb * 256 + tid;

    const int r0 = chunk * CHUNK_ROWS;

    const float*  ibase = masks    + (size_t)b * IMG + x;
    uint8_t*      obase = g_packed + (size_t)b * IMG + x;

    const uint64_t M35 = (1ULL << 35) - 1;
    const uint64_t M31 = (1ULL << 31) - 1;

    uint64_t bits = 0;

    // Prologue: rows r0-17 .. r0+16 (34 rows), two batches of 17 loads
    #pragma unroll 1
    for (int pb = 0; pb < 34; pb += 17) {
        float fv[17];
        #pragma unroll
        for (int i = 0; i < 17; ++i) {
            const int t = r0 - 17 + pb + i;     // t <= r0+16 <= 688 < H
            fv[i] = 0.0f;
            if (t >= 0) fv[i] = ibase[(size_t)t * W];
        }
        #pragma unroll
        for (int i = 0; i < 17; ++i)
            bits = (bits << 1) | (uint64_t)(fv[i] > 0.5f);
    }

    // Emit loop: batches of 16 rows; 16 outstanding LDGs per warp per batch.
    #pragma unroll 1
    for (int yb = 0; yb < CHUNK_ROWS; yb += 16) {
        float fv[16];
        #pragma unroll
        for (int i = 0; i < 16; ++i) {
            const int t = r0 + yb + i + 17;
            fv[i] = 0.0f;
            if (t < H) fv[i] = ibase[(size_t)t * W];
        }
        #pragma unroll
        for (int i = 0; i < 16; ++i) {
            bits = (bits << 1) | (uint64_t)(fv[i] > 0.5f);
            const int y = r0 + yb + i;
            uint32_t cnt    = (uint32_t)__popcll(bits & M35);          // rows y-17..y+17
            uint32_t center = (uint32_t)((bits >> 17) & 1ULL);         // row y
            uint32_t flag   = (((bits >> 2) & M31) != 0ULL) ? 1u : 0u; // rows y-15..y+15
            obase[(size_t)y * W] = (uint8_t)(cnt | (center << 6) | (flag << 7));
        }
    }
}

// ---------------------------------------------------------------------------
// Pass 2: per-row horizontal windows via one fused prefix sum.
// 192 threads per block, one row per block, 4 outputs per thread.
// Two __syncthreads; cross-warp offsets derived per-thread from broadcast LDS.
// grid: HB * H = 12288 blocks per half batch.
// ---------------------------------------------------------------------------
#define PAD 20

__global__ __launch_bounds__(192) void pass2_horizontal(float* __restrict__ out_rsm,
                                                        float* __restrict__ out_pfm,
                                                        int b_base) {
    __shared__ __align__(16) uint32_t sPp[PAD + W + 17];  // padded fused prefix
    __shared__ uint32_t sWarp[6];

    const int tid  = threadIdx.x;
    const int lane = tid & 31;
    const int wid  = tid >> 5;
    const int row  = b_base * H + blockIdx.x;   // global row = b*H + y
    const int x0   = tid * 4;

    // One u32 = this thread's 4 packed bytes (byte j -> x = x0 + j)
    const uint32_t w = ((const uint32_t*)(g_packed + (size_t)row * W))[tid];

    if (tid < PAD) sPp[tid] = 0;

    // Unpack: v = (cnt << 16) | flag
    uint32_t v0, v1, v2, v3;
    {
        uint32_t c0 = (w      ) & 63u, f0 = (w >> 7 ) & 1u;
        uint32_t c1 = (w >> 8 ) & 63u, f1 = (w >> 15) & 1u;
        uint32_t c2 = (w >> 16) & 63u, f2 = (w >> 23) & 1u;
        uint32_t c3 = (w >> 24) & 63u, f3 = (w >> 31);
        v0 = c0 * 65536u + f0;
        v1 = c1 * 65536u + f1;
        v2 = c2 * 65536u + f2;
        v3 = c3 * 65536u + f3;
    }
    const uint32_t s0 = v0;
    const uint32_t s1 = s0 + v1;
    const uint32_t s2 = s1 + v2;
    const uint32_t s3 = s2 + v3;

    // Warp inclusive scan of per-thread totals
    uint32_t sc = s3;
    #pragma unroll
    for (int d = 1; d < 32; d <<= 1) {
        uint32_t y = __shfl_up_sync(0xFFFFFFFFu, sc, d);
        if (lane >= d) sc += y;
    }
    if (lane == 31) sWarp[wid] = sc;
    __syncthreads();

    // Every thread derives its cross-warp exclusive offset and the row total
    // from the 6 per-warp totals (broadcast LDS, no serial thread, no barrier).
    uint32_t wt0 = sWarp[0], wt1 = sWarp[1], wt2 = sWarp[2];
    uint32_t wt3 = sWarp[3], wt4 = sWarp[4], wt5 = sWarp[5];
    uint32_t pre[6];
    pre[0] = 0;
    pre[1] = wt0;
    pre[2] = pre[1] + wt1;
    pre[3] = pre[2] + wt2;
    pre[4] = pre[3] + wt3;
    pre[5] = pre[4] + wt4;
    const uint32_t tot  = pre[5] + wt5;
    const uint32_t excl = (sc - s3) + pre[wid];

    // Inclusive prefix at x0..x0+3 (vector STS)
    {
        uint4 p;
        p.x = excl + s0;
        p.y = excl + s1;
        p.z = excl + s2;
        p.w = excl + s3;
        *(uint4*)&sPp[PAD + x0] = p;
    }
    // Right pad: replicate row total P[W-1]
    if (tid < 17) sPp[PAD + W + tid] = tot;
    __syncthreads();

    // Window reads (indices pre-shifted by PAD=20):
    //   lo35_j = sPp[x0+j+2], lo31_j = sPp[x0+j+4]
    //   hi31_j = sPp[x0+j+35], hi35_j = sPp[x0+j+37]
    const uint2 A01 = *(const uint2*)&sPp[x0 + 2];
    const uint4 A25 = *(const uint4*)&sPp[x0 + 4];
    const uint32_t b35 = sPp[x0 + 35];
    const uint4 B69 = *(const uint4*)&sPp[x0 + 36];
    const uint32_t b40 = sPp[x0 + 40];

    const float inv = 1.0f / (float)(RSM_K * RSM_K);

    // hi - lo has no cross-field borrow (both fields monotone)
    uint32_t d35_0 = B69.y - A01.x;
    uint32_t d35_1 = B69.z - A01.y;
    uint32_t d35_2 = B69.w - A25.x;
    uint32_t d35_3 = b40   - A25.y;

    uint32_t f31_0 = (b35   - A25.x) & 0xFFFFu;
    uint32_t f31_1 = (B69.x - A25.y) & 0xFFFFu;
    uint32_t f31_2 = (B69.y - A25.z) & 0xFFFFu;
    uint32_t f31_3 = (B69.z - A25.w) & 0xFFFFu;

    float4 rsm4;
    rsm4.x = (float)(d35_0 >> 16) * inv;
    rsm4.y = (float)(d35_1 >> 16) * inv;
    rsm4.z = (float)(d35_2 >> 16) * inv;
    rsm4.w = (float)(d35_3 >> 16) * inv;

    // pfm = center ? 1 : (f31 ? 0 : 2) == center + 2*(f31==0)
    float4 pfm4;
    pfm4.x = (float)(((w >> 6)  & 1u) + ((f31_0 == 0u) ? 2u : 0u));
    pfm4.y = (float)(((w >> 14) & 1u) + ((f31_1 == 0u) ? 2u : 0u));
    pfm4.z = (float)(((w >> 22) & 1u) + ((f31_2 == 0u) ? 2u : 0u));
    pfm4.w = (float)(((w >> 30) & 1u) + ((f31_3 == 0u) ? 2u : 0u));

    // Streaming stores: outputs are never re-read; keep L2 for g_packed.
    __stcs((float4*)(out_rsm + (size_t)row * W + x0), rsm4);
    __stcs((float4*)(out_pfm + (size_t)row * W + x0), pfm4);
}

// ---------------------------------------------------------------------------
// Static stream/event setup: created once at module load, before the harness's
// first memory checkpoint. No per-call state; identical DAG every call.
// ---------------------------------------------------------------------------
namespace {
struct StreamSetup {
    cudaStream_t s1 = nullptr;
    cudaEvent_t  evFork = nullptr, evJoin = nullptr;
    StreamSetup() {
        cudaStreamCreateWithFlags(&s1, cudaStreamNonBlocking);
        cudaEventCreateWithFlags(&evFork, cudaEventDisableTiming);
        cudaEventCreateWithFlags(&evJoin, cudaEventDisableTiming);
    }
};
StreamSetup g_ss;
}

extern "C" void kernel_launch(void* const* d_in, const int* in_sizes, int n_in,
                              void* d_out, int out_size) {
    const float* masks = (const float*)d_in[0];
    float* out = (float*)d_out;
    float* out_rsm = out;
    float* out_pfm = out + NPIX;

    // Same-phase half-batch fork (measured-best DAG, R14).
    cudaEventRecord(g_ss.evFork, 0);
    cudaStreamWaitEvent(g_ss.s1, g_ss.evFork, 0);

    // Half 0 on the default stream
    pass1_vertical<<<HB * 3 * CHUNKS, 256>>>(masks, 0);
    pass2_horizontal<<<HB * H, 192>>>(out_rsm, out_pfm, 0);

    // Half 1 on the branch stream
    pass1_vertical<<<HB * 3 * CHUNKS, 256, 0, g_ss.s1>>>(masks, HB);
    pass2_horizontal<<<HB * H, 192, 0, g_ss.s1>>>(out_rsm, out_pfm, HB);

    // Join
    cudaEventRecord(g_ss.evJoin, g_ss.s1);
    cudaStreamWaitEvent(0, g_ss.evJoin, 0);
}